// round 2
// baseline (speedup 1.0000x reference)
#include <cuda_runtime.h>
#include <cuda_bf16.h>
#include <math.h>

// ---------------------------------------------------------------------------
// GraphEncoder: featurize -> 3x GAT layer -> segment-max readout -> MLP heads
// Scratch is static __device__ arrays (no allocation allowed).
// ---------------------------------------------------------------------------

#define MAXN 50000
#define MAXE 800000
#define MAXB 500
#define NH 4
#define NF 64
#define HF 256         // NH*NF
#define GW 832         // 64 + 3*256
#define SLOPE 0.2f

__device__ float g_fbuf0[MAXN * HF];
__device__ float g_fbuf1[MAXN * HF];
__device__ float g_h[MAXN * HF];
__device__ float g_as[MAXN * NH];
__device__ float g_ad[MAXN * NH];
__device__ int   g_cnt[MAXN];
__device__ int   g_off[MAXN + 8];
__device__ int   g_curs[MAXN];
__device__ int   g_part[128];
__device__ int   g_esrc[MAXE + MAXN];
__device__ float g_gemb[MAXB * GW];
__device__ float g_lat[MAXB * HF];

// -------------------- small utility kernels --------------------
__global__ void k_zero_f(float* p, int n) {
    int i = blockIdx.x * blockDim.x + threadIdx.x;
    if (i < n) p[i] = 0.0f;
}
__global__ void k_set_i(int* p, int v, int n) {
    int i = blockIdx.x * blockDim.x + threadIdx.x;
    if (i < n) p[i] = v;
}
__global__ void k_copy_i(const int* __restrict__ a, int* __restrict__ b, int n) {
    int i = blockIdx.x * blockDim.x + threadIdx.x;
    if (i < n) b[i] = a[i];
}

// -------------------- node featurization (fused g0 segment-max) ------------
// blockDim = 64 (one node per block)
__global__ void k_featurize(const float* __restrict__ nf, const int* __restrict__ bmask,
                            const int* __restrict__ batch,
                            const float* __restrict__ bboxW, const float* __restrict__ bboxb,
                            const float* __restrict__ maskE,
                            const float* __restrict__ nodeW, const float* __restrict__ nodeb,
                            float* __restrict__ f0, unsigned* __restrict__ g) {
    __shared__ float c[128];
    int n = blockIdx.x;
    int t = threadIdx.x;
    float x = bboxb[t];
#pragma unroll
    for (int k = 0; k < 5; k++) x += nf[n * 5 + k] * bboxW[k * 64 + t];
    c[t] = fmaxf(x, 0.0f);
    c[64 + t] = fmaxf(maskE[bmask[n] * 64 + t], 0.0f);
    __syncthreads();
    float acc = nodeb[t];
#pragma unroll 8
    for (int k = 0; k < 128; k++) acc += c[k] * nodeW[k * 64 + t];
    acc = fmaxf(acc, 0.0f);
    f0[n * HF + t] = acc;
    atomicMax(&g[batch[n] * GW + t], __float_as_uint(acc));
}

// -------------------- CSR build --------------------
__global__ void k_count(const int* __restrict__ dst, int* __restrict__ cnt, int E) {
    int e = blockIdx.x * blockDim.x + threadIdx.x;
    if (e < E) atomicAdd(&cnt[dst[e]], 1);
}
__global__ void k_chunk_sum(const int* __restrict__ cnt, int* __restrict__ part, int n) {
    __shared__ int s[512];
    int t = threadIdx.x;
    int i = blockIdx.x * 512 + t;
    s[t] = (i < n) ? cnt[i] : 0;
    __syncthreads();
    for (int st = 256; st > 0; st >>= 1) {
        if (t < st) s[t] += s[t + st];
        __syncthreads();
    }
    if (t == 0) part[blockIdx.x] = s[0];
}
__global__ void k_scan_part(int* part, int np) {
    __shared__ int s[128];
    int t = threadIdx.x;
    int v = (t < np) ? part[t] : 0;
    s[t] = v;
    __syncthreads();
    for (int st = 1; st < 128; st <<= 1) {
        int a = (t >= st) ? s[t - st] : 0;
        __syncthreads();
        s[t] += a;
        __syncthreads();
    }
    if (t < np) part[t] = s[t] - v;  // exclusive
}
__global__ void k_chunk_scan(const int* __restrict__ cnt, const int* __restrict__ part,
                             int* __restrict__ off, int n) {
    __shared__ int s[512];
    int t = threadIdx.x;
    int i = blockIdx.x * 512 + t;
    int v = (i < n) ? cnt[i] : 0;
    s[t] = v;
    __syncthreads();
    for (int st = 1; st < 512; st <<= 1) {
        int a = (t >= st) ? s[t - st] : 0;
        __syncthreads();
        s[t] += a;
        __syncthreads();
    }
    int base = part[blockIdx.x];
    if (i < n) off[i] = base + s[t] - v;
    if (i == n - 1) off[n] = base + s[t];
}
__global__ void k_scatter(const int* __restrict__ src, const int* __restrict__ dst,
                          int* __restrict__ curs, int* __restrict__ esrc, int E) {
    int e = blockIdx.x * blockDim.x + threadIdx.x;
    if (e < E) {
        int p = atomicAdd(&curs[dst[e]], 1);
        esrc[p] = src[e];
    }
}
__global__ void k_selfloop(int* __restrict__ curs, int* __restrict__ esrc, int n) {
    int i = blockIdx.x * blockDim.x + threadIdx.x;
    if (i < n) {
        int p = atomicAdd(&curs[i], 1);
        esrc[p] = i;
    }
}

// -------------------- SGEMM: C[M,256] = A[M,:K] @ W[K,256] --------------------
// BM=128, BN=128, BK=16, blockDim=256, per-thread 8x8 tile.
__global__ __launch_bounds__(256) void k_gemm(const float* __restrict__ A,
                                              const float* __restrict__ W,
                                              float* __restrict__ C, int M, int K) {
    __shared__ float As[16][128];
    __shared__ float Bs[16][128];
    int tid = threadIdx.x;
    int brow = blockIdx.x * 128;
    int bcol = blockIdx.y * 128;
    int tx = tid % 16, ty = tid / 16;
    float acc[8][8];
#pragma unroll
    for (int i = 0; i < 8; i++)
#pragma unroll
        for (int j = 0; j < 8; j++) acc[i][j] = 0.0f;

    for (int k0 = 0; k0 < K; k0 += 16) {
#pragma unroll
        for (int r = 0; r < 2; r++) {
            int idx = tid + r * 256;       // 0..511 float4 slots
            int row = idx >> 2;
            int kc = (idx & 3) * 4;
            float4 v = make_float4(0.f, 0.f, 0.f, 0.f);
            int gr = brow + row;
            if (gr < M) v = *(const float4*)(A + (size_t)gr * HF + k0 + kc);
            As[kc + 0][row] = v.x;
            As[kc + 1][row] = v.y;
            As[kc + 2][row] = v.z;
            As[kc + 3][row] = v.w;
        }
#pragma unroll
        for (int r = 0; r < 2; r++) {
            int idx = tid + r * 256;
            int kr = idx >> 5;             // /32
            int c4 = (idx & 31) * 4;
            float4 v = *(const float4*)(W + (size_t)(k0 + kr) * HF + bcol + c4);
            *(float4*)&Bs[kr][c4] = v;
        }
        __syncthreads();
#pragma unroll
        for (int kk = 0; kk < 16; kk++) {
            float a[8], b[8];
#pragma unroll
            for (int i = 0; i < 8; i++) a[i] = As[kk][ty * 8 + i];
#pragma unroll
            for (int j = 0; j < 8; j++) b[j] = Bs[kk][tx * 8 + j];
#pragma unroll
            for (int i = 0; i < 8; i++)
#pragma unroll
                for (int j = 0; j < 8; j++) acc[i][j] += a[i] * b[j];
        }
        __syncthreads();
    }
#pragma unroll
    for (int i = 0; i < 8; i++) {
        int gr = brow + ty * 8 + i;
        if (gr < M) {
#pragma unroll
            for (int j = 0; j < 8; j += 4) {
                *(float4*)(C + (size_t)gr * HF + bcol + tx * 8 + j) =
                    make_float4(acc[i][j], acc[i][j + 1], acc[i][j + 2], acc[i][j + 3]);
            }
        }
    }
}

// -------------------- attention coefficients --------------------
// one warp per node: lanes split 4 heads x 8 lanes x 8 floats
__global__ void k_attn(const float* __restrict__ h, const float* __restrict__ att_s,
                       const float* __restrict__ att_d, float* __restrict__ asb,
                       float* __restrict__ adb, int N) {
    int warp = (blockIdx.x * blockDim.x + threadIdx.x) >> 5;
    int lane = threadIdx.x & 31;
    if (warp >= N) return;
    int head = lane >> 3;
    int fo = (lane & 7) * 8;
    const float* hr = h + (size_t)warp * HF + head * NF + fo;
    float4 v0 = *(const float4*)(hr);
    float4 v1 = *(const float4*)(hr + 4);
    const float* s0 = att_s + head * NF + fo;
    const float* d0 = att_d + head * NF + fo;
    float4 s4a = *(const float4*)(s0);
    float4 s4b = *(const float4*)(s0 + 4);
    float4 d4a = *(const float4*)(d0);
    float4 d4b = *(const float4*)(d0 + 4);
    float ss = v0.x * s4a.x + v0.y * s4a.y + v0.z * s4a.z + v0.w * s4a.w +
               v1.x * s4b.x + v1.y * s4b.y + v1.z * s4b.z + v1.w * s4b.w;
    float sd = v0.x * d4a.x + v0.y * d4a.y + v0.z * d4a.z + v0.w * d4a.w +
               v1.x * d4b.x + v1.y * d4b.y + v1.z * d4b.z + v1.w * d4b.w;
#pragma unroll
    for (int o = 4; o > 0; o >>= 1) {
        ss += __shfl_down_sync(0xffffffffu, ss, o, 8);
        sd += __shfl_down_sync(0xffffffffu, sd, o, 8);
    }
    if ((lane & 7) == 0) {
        asb[warp * NH + head] = ss;
        adb[warp * NH + head] = sd;
    }
}

// -------------------- GAT aggregation (softmax over in-edges) ---------------
// blockDim = 128: one node per block, one warp per head.
__global__ __launch_bounds__(128) void k_agg(const float* __restrict__ h,
                                             const float* __restrict__ asb,
                                             const float* __restrict__ adb,
                                             const int* __restrict__ off,
                                             const int* __restrict__ esrc,
                                             const float* __restrict__ bias,
                                             const int* __restrict__ batch,
                                             float* __restrict__ fnext,
                                             unsigned* __restrict__ g, int gcol0) {
    int n = blockIdx.x;
    int head = threadIdx.x >> 5;
    int lane = threadIdx.x & 31;
    int beg = off[n], end = off[n + 1];
    float ad = adb[n * NH + head];
    // pass 1: max
    float mx = -1e30f;
    for (int i = beg + lane; i < end; i += 32) {
        int s = esrc[i];
        float v = asb[s * NH + head] + ad;
        v = (v > 0.f) ? v : SLOPE * v;
        mx = fmaxf(mx, v);
    }
#pragma unroll
    for (int o = 16; o > 0; o >>= 1) mx = fmaxf(mx, __shfl_xor_sync(0xffffffffu, mx, o));
    // pass 2: exp-weighted accumulation
    float2 acc = make_float2(0.f, 0.f);
    float sum = 0.f;
    const float2* hb = (const float2*)h;
    for (int i = beg; i < end; i++) {
        int s = esrc[i];
        float v = asb[s * NH + head] + ad;
        v = (v > 0.f) ? v : SLOPE * v;
        float w = __expf(v - mx);
        sum += w;
        float2 hv = hb[(size_t)s * 128 + head * 32 + lane];
        acc.x += w * hv.x;
        acc.y += w * hv.y;
    }
    float inv = 1.0f / sum;
    int c = head * NF + lane * 2;
    float o0 = fmaxf(acc.x * inv + bias[c], 0.f);
    float o1 = fmaxf(acc.y * inv + bias[c + 1], 0.f);
    fnext[(size_t)n * HF + c] = o0;
    fnext[(size_t)n * HF + c + 1] = o1;
    int b = batch[n];
    atomicMax(&g[b * GW + gcol0 + c], __float_as_uint(o0));
    atomicMax(&g[b * GW + gcol0 + c + 1], __float_as_uint(o1));
}

// -------------------- readout MLPs --------------------
__global__ void k_agg_mlp(const float* __restrict__ g, const float* __restrict__ aggW,
                          const float* __restrict__ aggb, float* __restrict__ lat) {
    __shared__ float s[GW];
    int r = blockIdx.x, t = threadIdx.x;
    for (int i = t; i < GW; i += 256) s[i] = g[r * GW + i];
    __syncthreads();
    float acc = aggb[t];
#pragma unroll 8
    for (int k = 0; k < GW; k++) acc += s[k] * aggW[k * HF + t];
    lat[r * HF + t] = acc;
}
__global__ void k_heads(const float* __restrict__ lat, const float* __restrict__ muW,
                        const float* __restrict__ mub, const float* __restrict__ vW,
                        const float* __restrict__ vb, float* __restrict__ out, int B) {
    __shared__ float s[HF];
    int r = blockIdx.x, t = threadIdx.x;
    s[t] = lat[r * HF + t];
    __syncthreads();
    float m = mub[t], v = vb[t];
#pragma unroll 8
    for (int k = 0; k < HF; k++) {
        float x = s[k];
        m += x * muW[k * HF + t];
        v += x * vW[k * HF + t];
    }
    out[r * HF + t] = m;
    out[(size_t)B * HF + r * HF + t] = v;
}

// ---------------------------------------------------------------------------
extern "C" void kernel_launch(void* const* d_in, const int* in_sizes, int n_in,
                              void* d_out, int out_size) {
    const float* nf    = (const float*)d_in[0];
    const int*   bmask = (const int*)d_in[1];
    const int*   batch = (const int*)d_in[2];
    const int*   eidx  = (const int*)d_in[3];
    const float* bboxW = (const float*)d_in[4];
    const float* bboxb = (const float*)d_in[5];
    const float* maskE = (const float*)d_in[6];
    const float* nodeW = (const float*)d_in[7];
    const float* nodeb = (const float*)d_in[8];
    const float* w[3]  = {(const float*)d_in[9],  (const float*)d_in[13], (const float*)d_in[17]};
    const float* as_[3] = {(const float*)d_in[10], (const float*)d_in[14], (const float*)d_in[18]};
    const float* ad_[3] = {(const float*)d_in[11], (const float*)d_in[15], (const float*)d_in[19]};
    const float* bb[3] = {(const float*)d_in[12], (const float*)d_in[16], (const float*)d_in[20]};
    const float* aggW  = (const float*)d_in[21];
    const float* aggb  = (const float*)d_in[22];
    const float* muW   = (const float*)d_in[23];
    const float* mub   = (const float*)d_in[24];
    const float* vW    = (const float*)d_in[25];
    const float* vb    = (const float*)d_in[26];
    float* out = (float*)d_out;

    int N = in_sizes[0] / 5;
    int E = in_sizes[3] / 2;
    int B = out_size / (2 * HF);
    const int* src = eidx;
    const int* dst = eidx + E;

    float *fb0, *fb1, *hbuf, *asb, *adb, *gemb, *lat;
    int *cnt, *off, *curs, *part, *esrc;
    cudaGetSymbolAddress((void**)&fb0, g_fbuf0);
    cudaGetSymbolAddress((void**)&fb1, g_fbuf1);
    cudaGetSymbolAddress((void**)&hbuf, g_h);
    cudaGetSymbolAddress((void**)&asb, g_as);
    cudaGetSymbolAddress((void**)&adb, g_ad);
    cudaGetSymbolAddress((void**)&cnt, g_cnt);
    cudaGetSymbolAddress((void**)&off, g_off);
    cudaGetSymbolAddress((void**)&curs, g_curs);
    cudaGetSymbolAddress((void**)&part, g_part);
    cudaGetSymbolAddress((void**)&esrc, g_esrc);
    cudaGetSymbolAddress((void**)&gemb, g_gemb);
    cudaGetSymbolAddress((void**)&lat, g_lat);

    // zero graph embeddings
    k_zero_f<<<(B * GW + 255) / 256, 256>>>(gemb, B * GW);
    // featurize nodes (fused first segment-max)
    k_featurize<<<N, 64>>>(nf, bmask, batch, bboxW, bboxb, maskE, nodeW, nodeb,
                           fb0, (unsigned*)gemb);
    // CSR build by dst (counting sort; +1 everywhere for self loops)
    k_set_i<<<(N + 255) / 256, 256>>>(cnt, 1, N);
    k_count<<<(E + 255) / 256, 256>>>(dst, cnt, E);
    int nch = (N + 511) / 512;
    k_chunk_sum<<<nch, 512>>>(cnt, part, N);
    k_scan_part<<<1, 128>>>(part, nch);
    k_chunk_scan<<<nch, 512>>>(cnt, part, off, N);
    k_copy_i<<<(N + 255) / 256, 256>>>(off, curs, N);
    k_scatter<<<(E + 255) / 256, 256>>>(src, dst, curs, esrc, E);
    k_selfloop<<<(N + 255) / 256, 256>>>(curs, esrc, N);

    // 3 GAT layers
    float* cur = fb0;
    float* nxt = fb1;
    int Kin[3] = {64, 256, 256};
    int gcol0[3] = {64, 64 + 256, 64 + 512};
    dim3 ggrid((N + 127) / 128, 2);
    for (int L = 0; L < 3; L++) {
        k_gemm<<<ggrid, 256>>>(cur, w[L], hbuf, N, Kin[L]);
        k_attn<<<(N + 7) / 8, 256>>>(hbuf, as_[L], ad_[L], asb, adb, N);
        k_agg<<<N, 128>>>(hbuf, asb, adb, off, esrc, bb[L], batch, nxt,
                          (unsigned*)gemb, gcol0[L]);
        float* t = cur; cur = nxt; nxt = t;
    }

    // readout
    k_agg_mlp<<<B, 256>>>(gemb, aggW, aggb, lat);
    k_heads<<<B, 256>>>(lat, muW, mub, vW, vb, out, B);
}